// round 9
// baseline (speedup 1.0000x reference)
#include <cuda_runtime.h>
#include <cuda_bf16.h>
#include <cstdint>

// ---------------------------------------------------------------------------
// YOLO loss (nc=1).  B=64, N=32, A=3, grids {160,80,40}, pred [B,18,G,G].
//
// loss = 0.05 * sum_s box_sq[s]/n_pos[s]
//      +        sum_s ( pos_plus[s]/n_pos[s] + (S_all[s]-pos_neg[s])/n_neg[s] )
//
// LDG path is stuck at ~770GB/s regardless of MLP/occupancy (R2-R8), so the
// dense pass now uses cp.async.bulk (TMA) into SMEM, double-buffered, and
// computes softplus from SMEM.
//   blocks [0,24):       192 warp-tasks (scale,batch) target matching
//   blocks [24,216):     s0 — one obj plane each (102400B = 8 x 12800B chunks)
//   blocks [216,264):    s1 — four obj planes each (4 x 2 x 12800B chunks)
//   blocks [264,288):    s2 — eight obj planes each (8 x 6400B chunks)
//   last block (ticket) reduces partials and writes the loss.
// ---------------------------------------------------------------------------

#define NN 32
#define TGT_BLOCKS 24
#define S0_BLOCKS 192
#define S1_BLOCKS 48
#define S2_BLOCKS 24
#define DENSE_BLOCKS (S0_BLOCKS + S1_BLOCKS + S2_BLOCKS)   // 264
#define TOTAL_BLOCKS (TGT_BLOCKS + DENSE_BLOCKS)           // 288
#define CHUNK 12800
#define NSLOT 8

__device__ double   g_part[DENSE_BLOCKS];  // dense per-block partials
__device__ float4   g_tpart[192];          // target partials: sq, sp-, sp+, cnt
__device__ unsigned g_ticket;

// ---------------- PTX helpers ----------------
__device__ __forceinline__ uint32_t smem_u32(const void* p) {
    uint32_t a;
    asm("{ .reg .u64 t; cvta.to.shared.u64 t, %1; cvt.u32.u64 %0, t; }"
        : "=r"(a) : "l"(p));
    return a;
}
__device__ __forceinline__ void mbar_init(uint32_t addr, uint32_t cnt) {
    asm volatile("mbarrier.init.shared.b64 [%0], %1;" :: "r"(addr), "r"(cnt) : "memory");
}
__device__ __forceinline__ void fence_proxy_async_cta() {
    asm volatile("fence.proxy.async.shared::cta;" ::: "memory");
}
__device__ __forceinline__ void mbar_expect_tx(uint32_t addr, uint32_t bytes) {
    asm volatile("mbarrier.arrive.expect_tx.shared.b64 _, [%0], %1;"
                 :: "r"(addr), "r"(bytes) : "memory");
}
__device__ __forceinline__ void bulk_copy(uint32_t dst_smem, const void* src,
                                          uint32_t bytes, uint32_t mbar) {
    asm volatile("cp.async.bulk.shared::cta.global.mbarrier::complete_tx::bytes "
                 "[%0], [%1], %2, [%3];"
                 :: "r"(dst_smem), "l"(src), "r"(bytes), "r"(mbar) : "memory");
}
__device__ __forceinline__ void mbar_wait(uint32_t addr, uint32_t parity) {
    asm volatile(
        "{\n\t"
        ".reg .pred P;\n\t"
        "WAIT_%=:\n\t"
        "mbarrier.try_wait.parity.acquire.cta.shared::cta.b64 P, [%0], %1;\n\t"
        "@!P bra WAIT_%=;\n\t"
        "}"
        :: "r"(addr), "r"(parity) : "memory");
}

// ---------------- math ----------------
__device__ __forceinline__ float sp(float x) {
    return fmaxf(x, 0.0f) + __logf(1.0f + __expf(-fabsf(x)));
}

struct Acc { float l0, l1, g0, g1; };

__device__ __forceinline__ void accum4(float4 v, Acc& a) {
    a.l0 += fmaxf(v.x, 0.0f) + fmaxf(v.y, 0.0f);
    a.l1 += fmaxf(v.z, 0.0f) + fmaxf(v.w, 0.0f);
    a.g0 += __log2f(1.0f + __expf(-fabsf(v.x))) + __log2f(1.0f + __expf(-fabsf(v.y)));
    a.g1 += __log2f(1.0f + __expf(-fabsf(v.z))) + __log2f(1.0f + __expf(-fabsf(v.w)));
}

// unit k of dense block d -> (gmem src, bytes)
__device__ __forceinline__ void unit_info(int d, int k,
        const char* p0, const char* p1, const char* p2,
        const char*& src, uint32_t& bytes) {
    if (d < S0_BLOCKS) {
        // s0 plane: 6*102400 stride, obj at +409600
        src = p0 + (size_t)d * 614400 + 409600 + (size_t)k * 12800;
        bytes = 12800;
    } else if (d < S0_BLOCKS + S1_BLOCKS) {
        int plane = 4 * (d - S0_BLOCKS) + (k >> 1);
        src = p1 + (size_t)plane * 153600 + 102400 + (size_t)(k & 1) * 12800;
        bytes = 12800;
    } else {
        int plane = 8 * (d - S0_BLOCKS - S1_BLOCKS) + k;
        src = p2 + (size_t)plane * 38400 + 25600;
        bytes = 6400;
    }
}

__global__ void __launch_bounds__(256, 2) yolo_kernel(
        const float* __restrict__ pred0,
        const float* __restrict__ pred1,
        const float* __restrict__ pred2,
        const float* __restrict__ boxes,
        const float* __restrict__ anchors,
        float* __restrict__ out) {
    const int bid  = blockIdx.x;
    const int tid  = threadIdx.x;
    const int lane = tid & 31;
    const int wid  = tid >> 5;

    __shared__ alignas(128) char sbuf[2][CHUNK];
    __shared__ alignas(8) unsigned long long mbar[2];
    __shared__ float  warpsum[8];
    __shared__ int    keys[8][NN];
    __shared__ double dsh[3][8];
    __shared__ double tsh[4][6];
    __shared__ bool   s_last;

    if (bid >= TGT_BLOCKS) {
        // ---------------- dense objectness pass via TMA bulk copies ----------------
        const int d = bid - TGT_BLOCKS;
        const char* p0 = (const char*)pred0;
        const char* p1 = (const char*)pred1;
        const char* p2 = (const char*)pred2;
        const uint32_t mb0 = smem_u32(&mbar[0]);
        const uint32_t mb1 = smem_u32(&mbar[1]);
        const uint32_t sb0 = smem_u32(&sbuf[0][0]);
        const uint32_t sb1 = smem_u32(&sbuf[1][0]);
        const int nf4 = (d < S0_BLOCKS + S1_BLOCKS) ? 800 : 400;

        if (tid == 0) {
            mbar_init(mb0, 1);
            mbar_init(mb1, 1);
            fence_proxy_async_cta();
        }
        __syncthreads();

        if (tid == 0) {
            const char* src; uint32_t bytes;
            unit_info(d, 0, p0, p1, p2, src, bytes);
            mbar_expect_tx(mb0, bytes);
            bulk_copy(sb0, src, bytes, mb0);
            unit_info(d, 1, p0, p1, p2, src, bytes);
            mbar_expect_tx(mb1, bytes);
            bulk_copy(sb1, src, bytes, mb1);
        }

        Acc a = {0.0f, 0.0f, 0.0f, 0.0f};
        #pragma unroll 1
        for (int k = 0; k < NSLOT; k++) {
            const uint32_t mbk = (k & 1) ? mb1 : mb0;
            mbar_wait(mbk, (k >> 1) & 1);
            const float4* sb = reinterpret_cast<const float4*>((k & 1) ? sbuf[1] : sbuf[0]);
            for (int i = tid; i < nf4; i += 256)
                accum4(sb[i], a);
            __syncthreads();                     // everyone done reading this buffer
            if (k + 2 < NSLOT && tid == 0) {
                const char* src; uint32_t bytes;
                unit_info(d, k + 2, p0, p1, p2, src, bytes);
                mbar_expect_tx(mbk, bytes);
                bulk_copy((k & 1) ? sb1 : sb0, src, bytes, mbk);
            }
        }

        float v = (a.l0 + a.l1) + 0.69314718055994531f * (a.g0 + a.g1);
        #pragma unroll
        for (int o = 16; o > 0; o >>= 1)
            v += __shfl_down_sync(0xffffffffu, v, o);
        if (lane == 0) warpsum[wid] = v;
        __syncthreads();
        if (tid == 0) {
            double t = 0.0;
            #pragma unroll
            for (int w = 0; w < 8; w++) t += (double)warpsum[w];
            g_part[d] = t;
        }
    } else {
        // ---------------- sparse target pass: one (scale,batch) per warp ----------------
        const int task = bid * 8 + wid;          // 0..191
        const int s = task >> 6;
        const int b = task & 63;
        const int n = lane;

        const int G = (s == 0) ? 160 : (s == 1) ? 80 : 40;
        const float* pred = (s == 0) ? pred0 : (s == 1) ? pred1 : pred2;
        const int HW = G * G;

        float4 bx = reinterpret_cast<const float4*>(boxes)[b * NN + n];
        float gx = bx.x * (float)G;
        float gy = bx.y * (float)G;
        float gw = bx.z * (float)G;
        float gh = bx.w * (float)G;
        int gi = (int)gx;
        int gj = (int)gy;

        float bestIou = -1.0f;
        float aw = 1.0f, ah = 1.0f;
        int best = 0;
        #pragma unroll
        for (int a = 0; a < 3; a++) {
            float Aw = anchors[s * 6 + a * 2 + 0];
            float Ah = anchors[s * 6 + a * 2 + 1];
            float rw = __fdiv_rn(Aw, gw);
            float rh = __fdiv_rn(Ah, gh);
            float iw = fminf(rw, __fdiv_rn(1.0f, rw));
            float ih = fminf(rh, __fdiv_rn(1.0f, rh));
            float iou = iw * ih;
            if (iou > bestIou) { bestIou = iou; best = a; aw = Aw; ah = Ah; }
        }

        int key = (best * G + gj) * G + gi;
        keys[wid][n] = key;
        __syncwarp();
        bool live = true;
        for (int m = n + 1; m < NN; m++)
            if (keys[wid][m] == key) { live = false; break; }

        float sq = 0.0f, spp = 0.0f, spm = 0.0f, cnt = 0.0f;
        if (live) {
            size_t base = (size_t)(b * 18 + best * 6) * HW + (size_t)gj * G + gi;
            float p0 = __ldg(pred + base);
            float p1 = __ldg(pred + base + (size_t)HW);
            float p2 = __ldg(pred + base + (size_t)2 * HW);
            float p3 = __ldg(pred + base + (size_t)3 * HW);
            float p4 = __ldg(pred + base + (size_t)4 * HW);

            float tx = gx - (float)gi;
            float ty = gy - (float)gj;
            float tw = logf(__fdiv_rn(gw, aw) + 1e-16f);
            float th = logf(__fdiv_rn(gh, ah) + 1e-16f);

            float d0 = p0 - tx, d1 = p1 - ty, d2 = p2 - tw, d3 = p3 - th;
            sq  = d0 * d0 + d1 * d1 + d2 * d2 + d3 * d3;
            spm = sp(-p4);
            spp = sp(p4);
            cnt = 1.0f;
        }

        #pragma unroll
        for (int o = 16; o > 0; o >>= 1) {
            sq  += __shfl_down_sync(0xffffffffu, sq,  o);
            spm += __shfl_down_sync(0xffffffffu, spm, o);
            spp += __shfl_down_sync(0xffffffffu, spp, o);
            cnt += __shfl_down_sync(0xffffffffu, cnt, o);
        }
        if (n == 0)
            g_tpart[task] = make_float4(sq, spm, spp, cnt);
        __syncthreads();
    }

    // ---------------- last-block finalize ----------------
    if (tid == 0) {
        __threadfence();
        unsigned t = atomicAdd(&g_ticket, 1u);
        s_last = (t == TOTAL_BLOCKS - 1);
    }
    __syncthreads();
    if (s_last) {
        __threadfence();
        double v0 = 0.0, v1 = 0.0, v2 = 0.0;
        if (tid < S0_BLOCKS) v0 = ((volatile double*)g_part)[tid];
        if (tid < S1_BLOCKS) v1 = ((volatile double*)g_part)[S0_BLOCKS + tid];
        if (tid < S2_BLOCKS) v2 = ((volatile double*)g_part)[S0_BLOCKS + S1_BLOCKS + tid];
        #pragma unroll
        for (int o = 16; o > 0; o >>= 1) {
            v0 += __shfl_down_sync(0xffffffffu, v0, o);
            v1 += __shfl_down_sync(0xffffffffu, v1, o);
            v2 += __shfl_down_sync(0xffffffffu, v2, o);
        }
        if (lane == 0) { dsh[0][wid] = v0; dsh[1][wid] = v1; dsh[2][wid] = v2; }

        if (wid < 6) {
            const volatile float* tp = (const volatile float*)g_tpart;
            int o4 = (wid * 32 + lane) * 4;
            double a  = (double)tp[o4 + 0];
            double b  = (double)tp[o4 + 1];
            double c  = (double)tp[o4 + 2];
            double dd = (double)tp[o4 + 3];
            #pragma unroll
            for (int o = 16; o > 0; o >>= 1) {
                a  += __shfl_down_sync(0xffffffffu, a,  o);
                b  += __shfl_down_sync(0xffffffffu, b,  o);
                c  += __shfl_down_sync(0xffffffffu, c,  o);
                dd += __shfl_down_sync(0xffffffffu, dd, o);
            }
            if (lane == 0) { tsh[0][wid] = a; tsh[1][wid] = b; tsh[2][wid] = c; tsh[3][wid] = dd; }
        }
        __syncthreads();

        if (tid == 0) {
            double sall0 = 0.0, sall1 = 0.0, sall2 = 0.0;
            #pragma unroll
            for (int w = 0; w < 8; w++) {
                sall0 += dsh[0][w]; sall1 += dsh[1][w]; sall2 += dsh[2][w];
            }
            const double cells[3] = {4915200.0, 1228800.0, 307200.0};
            double sall[3] = {sall0, sall1, sall2};
            double loss = 0.0;
            #pragma unroll
            for (int s = 0; s < 3; s++) {
                double box = tsh[0][2 * s] + tsh[0][2 * s + 1];
                double pp  = tsh[1][2 * s] + tsh[1][2 * s + 1];
                double pn  = tsh[2][2 * s] + tsh[2][2 * s + 1];
                double np  = tsh[3][2 * s] + tsh[3][2 * s + 1];
                double nn  = cells[s] - np;
                loss += 0.05 * box / np + pp / np + (sall[s] - pn) / nn;
            }
            g_ticket = 0u;           // reset for next replay
            out[0] = (float)loss;
        }
    }
}

extern "C" void kernel_launch(void* const* d_in, const int* in_sizes, int n_in,
                              void* d_out, int out_size) {
    (void)in_sizes; (void)n_in; (void)out_size;
    const float* pred0   = (const float*)d_in[0];
    const float* pred1   = (const float*)d_in[1];
    const float* pred2   = (const float*)d_in[2];
    const float* boxes   = (const float*)d_in[3];
    // d_in[4] = labels (unused, nc==1)
    const float* anchors = (const float*)d_in[5];
    float* out = (float*)d_out;

    yolo_kernel<<<TOTAL_BLOCKS, 256>>>(pred0, pred1, pred2, boxes, anchors, out);
}